// round 5
// baseline (speedup 1.0000x reference)
#include <cuda_runtime.h>

#define NS 100000
#define ND 100000
#define NE 1600000
#define DIN 256
#define NH 4
#define DH 32
#define HD 128
#define NEG 0.2f

// ---- scratch (device globals: no allocations allowed) ----
__device__ float g_fs[(size_t)NS * HD];      // 51.2 MB: transformed src feats
__device__ float g_esrc[NS * NH];
__device__ float g_edst[ND * NH];
__device__ float g_vdst[NH * DIN];           // [h][k] layout for dst GEMV
__device__ int   g_count[ND];                // in-degree histogram
__device__ int   g_row[ND];                  // CSR row starts (exclusive scan)
__device__ int   g_cur[ND];                  // scatter cursors
__device__ int   g_ssorted[NE];              // src idx sorted by dst
__device__ int   g_bsum;                     // (unused spare)

// ---------------------------------------------------------------------------
// v_dst[h][k] = sum_d w_dst[k, h*32+d] * attn[h, d]
// ---------------------------------------------------------------------------
__global__ void k_v(const float* __restrict__ w_dst,
                    const float* __restrict__ attn) {
    int k = threadIdx.x;  // 0..255
    #pragma unroll
    for (int h = 0; h < NH; h++) {
        float s2 = 0.f;
        #pragma unroll 8
        for (int d = 0; d < DH; d++)
            s2 += w_dst[k * HD + h * DH + d] * attn[h * 2 * DH + d];
        g_vdst[h * DIN + k] = s2;
    }
}

// ---------------------------------------------------------------------------
// zero: g_esrc (NS*NH floats) and g_count (ND ints)
// ---------------------------------------------------------------------------
__global__ void k_zero() {
    const int n_es4 = NS * NH / 4;
    const int n_ct4 = ND / 4;
    int i = blockIdx.x * blockDim.x + threadIdx.x;
    if (i < n_es4) ((float4*)g_esrc)[i] = make_float4(0.f, 0.f, 0.f, 0.f);
    else if (i < n_es4 + n_ct4) ((int4*)g_count)[i - n_es4] = make_int4(0, 0, 0, 0);
}

// ---------------------------------------------------------------------------
// TF32 helpers
// ---------------------------------------------------------------------------
__device__ __forceinline__ unsigned f2tf32(float f) {
    unsigned u;
    asm("cvt.rna.tf32.f32 %0, %1;" : "=r"(u) : "f"(f));
    return u;
}
__device__ __forceinline__ void mma_tf32(float* c, const unsigned* a, const unsigned* b) {
    asm volatile(
        "mma.sync.aligned.m16n8k8.row.col.f32.tf32.tf32.f32 "
        "{%0,%1,%2,%3}, {%4,%5,%6,%7}, {%8,%9}, {%0,%1,%2,%3};\n"
        : "+f"(c[0]), "+f"(c[1]), "+f"(c[2]), "+f"(c[3])
        : "r"(a[0]), "r"(a[1]), "r"(a[2]), "r"(a[3]), "r"(b[0]), "r"(b[1]));
}
__device__ __forceinline__ void red_add_v2(float* p, float x, float y) {
    asm volatile("red.global.add.v2.f32 [%0], {%1,%2};"
                 :: "l"(p), "f"(x), "f"(y) : "memory");
}

// ---------------------------------------------------------------------------
// 3xTF32 GEMM: g_fs = feat_src @ w_src  (M=100000, N=128, K=256)
// Epilogue fuses e_src[n,h] = sum_d fs[n,h*32+d]*attn[h,32+d] via red.add.
// ---------------------------------------------------------------------------
#define PA 136
#define PB 136

__global__ __launch_bounds__(256, 1)
void k_gemm(const float* __restrict__ A, const float* __restrict__ B,
            const float* __restrict__ attn, int M) {
    __shared__ unsigned Ah[16 * PA], Al[16 * PA];
    __shared__ unsigned Bh[16 * PB], Bl[16 * PB];
    __shared__ float at[HD];

    const int tid = threadIdx.x;
    const int bm = blockIdx.x * 128;
    const int wid = tid >> 5;
    const int lane = tid & 31;
    const int warpM = wid >> 1;          // 0..3
    const int warpN = wid & 1;           // 0..1
    const int g = lane >> 2;             // 0..7
    const int t = lane & 3;              // 0..3

    if (tid < HD)
        at[tid] = attn[(tid >> 5) * (2 * DH) + DH + (tid & 31)];

    float acc[2][8][4];
    #pragma unroll
    for (int m = 0; m < 2; m++)
        #pragma unroll
        for (int n = 0; n < 8; n++)
            #pragma unroll
            for (int q = 0; q < 4; q++) acc[m][n][q] = 0.f;

    for (int k0 = 0; k0 < DIN; k0 += 16) {
        #pragma unroll
        for (int i = 0; i < 2; i++) {
            int idx = tid * 2 + i;          // 0..511
            int r = idx >> 2;
            int c4 = (idx & 3) * 4;
            int grow = bm + r;
            if (grow >= M) grow = M - 1;
            float4 a4 = *(const float4*)&A[(size_t)grow * DIN + k0 + c4];
            float av[4] = {a4.x, a4.y, a4.z, a4.w};
            #pragma unroll
            for (int q = 0; q < 4; q++) {
                unsigned hi = f2tf32(av[q]);
                float lo_f = av[q] - __uint_as_float(hi);
                Ah[(c4 + q) * PA + r] = hi;
                Al[(c4 + q) * PA + r] = f2tf32(lo_f);
            }
            int rb = idx >> 5;
            int cb = (idx & 31) * 4;
            float4 b4 = *(const float4*)&B[(size_t)(k0 + rb) * HD + cb];
            float bv[4] = {b4.x, b4.y, b4.z, b4.w};
            #pragma unroll
            for (int q = 0; q < 4; q++) {
                unsigned hi = f2tf32(bv[q]);
                float lo_f = bv[q] - __uint_as_float(hi);
                Bh[rb * PB + cb + q] = hi;
                Bl[rb * PB + cb + q] = f2tf32(lo_f);
            }
        }
        __syncthreads();

        #pragma unroll
        for (int s = 0; s < 2; s++) {
            const int kk = s * 8;
            unsigned ah[2][4], al[2][4];
            #pragma unroll
            for (int m = 0; m < 2; m++) {
                int row = warpM * 32 + m * 16 + g;
                ah[m][0] = Ah[(kk + t) * PA + row];
                ah[m][1] = Ah[(kk + t) * PA + row + 8];
                ah[m][2] = Ah[(kk + t + 4) * PA + row];
                ah[m][3] = Ah[(kk + t + 4) * PA + row + 8];
                al[m][0] = Al[(kk + t) * PA + row];
                al[m][1] = Al[(kk + t) * PA + row + 8];
                al[m][2] = Al[(kk + t + 4) * PA + row];
                al[m][3] = Al[(kk + t + 4) * PA + row + 8];
            }
            #pragma unroll
            for (int n = 0; n < 8; n++) {
                int col = warpN * 64 + n * 8 + g;
                unsigned bh[2], bl[2];
                bh[0] = Bh[(kk + t) * PB + col];
                bh[1] = Bh[(kk + t + 4) * PB + col];
                bl[0] = Bl[(kk + t) * PB + col];
                bl[1] = Bl[(kk + t + 4) * PB + col];
                #pragma unroll
                for (int m = 0; m < 2; m++) {
                    mma_tf32(acc[m][n], ah[m], bh);
                    mma_tf32(acc[m][n], al[m], bh);
                    mma_tf32(acc[m][n], ah[m], bl);
                }
            }
        }
        __syncthreads();
    }

    const int hA = 2 * warpN;
    #pragma unroll
    for (int m = 0; m < 2; m++) {
        int row0 = bm + warpM * 32 + m * 16 + g;
        int row1 = row0 + 8;
        float s0a = 0.f, s0b = 0.f, s1a = 0.f, s1b = 0.f;
        #pragma unroll
        for (int n = 0; n < 8; n++) {
            int col = warpN * 64 + n * 8 + 2 * t;
            float a0 = at[col], a1 = at[col + 1];
            if (n < 4) { s0a += acc[m][n][0] * a0 + acc[m][n][1] * a1;
                         s1a += acc[m][n][2] * a0 + acc[m][n][3] * a1; }
            else       { s0b += acc[m][n][0] * a0 + acc[m][n][1] * a1;
                         s1b += acc[m][n][2] * a0 + acc[m][n][3] * a1; }
            if (row0 < M)
                *(float2*)&g_fs[(size_t)row0 * HD + col] = make_float2(acc[m][n][0], acc[m][n][1]);
            if (row1 < M)
                *(float2*)&g_fs[(size_t)row1 * HD + col] = make_float2(acc[m][n][2], acc[m][n][3]);
        }
        if (row0 < M) red_add_v2(&g_esrc[row0 * NH + hA], s0a, s0b);
        if (row1 < M) red_add_v2(&g_esrc[row1 * NH + hA], s1a, s1b);
    }
}

// ---------------------------------------------------------------------------
// GEMV: e_dst[n,h] = feat_dst[n,:] dot v_dst[h,:]  — one warp per node
// ---------------------------------------------------------------------------
__global__ __launch_bounds__(256)
void k_e(const float* __restrict__ feat, int n) {
    __shared__ float vs[NH][DIN];
    for (int i = threadIdx.x; i < NH * DIN; i += blockDim.x)
        vs[i / DIN][i % DIN] = g_vdst[i];
    __syncthreads();

    int warp = (blockIdx.x * blockDim.x + threadIdx.x) >> 5;
    int lane = threadIdx.x & 31;
    int nw = (gridDim.x * blockDim.x) >> 5;
    for (int node = warp; node < n; node += nw) {
        float acc[NH] = {0.f, 0.f, 0.f, 0.f};
        #pragma unroll
        for (int j = 0; j < DIN / 128; j++) {
            int k4 = j * 128 + lane * 4;
            float4 x = *(const float4*)&feat[(size_t)node * DIN + k4];
            #pragma unroll
            for (int h = 0; h < NH; h++) {
                float4 vv = *(const float4*)&vs[h][k4];
                acc[h] += x.x * vv.x + x.y * vv.y + x.z * vv.z + x.w * vv.w;
            }
        }
        #pragma unroll
        for (int h = 0; h < NH; h++) {
            #pragma unroll
            for (int off = 16; off > 0; off >>= 1)
                acc[h] += __shfl_xor_sync(0xffffffffu, acc[h], off);
        }
        if (lane == 0)
            *(float4*)&g_edst[node * NH] = make_float4(acc[0], acc[1], acc[2], acc[3]);
    }
}

// ---------------------------------------------------------------------------
// CSR build: histogram, chunked single-block scan, scatter
// ---------------------------------------------------------------------------
__global__ void k_hist(const int* __restrict__ dst) {
    int e = blockIdx.x * blockDim.x + threadIdx.x;
    if (e < NE) atomicAdd(&g_count[dst[e]], 1);
}

#define SCAN_T 1024
#define CHUNK ((ND + SCAN_T - 1) / SCAN_T)   // 98

__global__ __launch_bounds__(SCAN_T)
void k_scan() {
    __shared__ int sums[SCAN_T];
    int t = threadIdx.x;
    int begin = t * CHUNK;
    int end = begin + CHUNK; if (end > ND) end = ND;
    int s = 0;
    for (int i = begin; i < end; i++) s += g_count[i];
    sums[t] = s;
    __syncthreads();
    // Hillis-Steele inclusive scan
    for (int d = 1; d < SCAN_T; d <<= 1) {
        int v = 0;
        if (t >= d) v = sums[t - d];
        __syncthreads();
        if (t >= d) sums[t] += v;
        __syncthreads();
    }
    int off = sums[t] - s;   // exclusive prefix for this chunk
    for (int i = begin; i < end; i++) {
        int c = g_count[i];
        g_row[i] = off;
        g_cur[i] = off;
        off += c;
    }
}

__global__ void k_scatter(const int* __restrict__ src, const int* __restrict__ dst) {
    int e = blockIdx.x * blockDim.x + threadIdx.x;
    if (e < NE) {
        int d = dst[e];
        int pos = atomicAdd(&g_cur[d], 1);
        g_ssorted[pos] = src[e];
    }
}

// ---------------------------------------------------------------------------
// Gather: one warp per dst node. Registers accumulate sum(fs[s]*ex) and
// sum(ex); write relu(acc/sum) directly. No atomics, no out-zeroing.
// ---------------------------------------------------------------------------
__global__ __launch_bounds__(256)
void k_gather(float* __restrict__ out) {
    int warp = (blockIdx.x * blockDim.x + threadIdx.x) >> 5;
    int lane = threadIdx.x & 31;
    int nw = (gridDim.x * blockDim.x) >> 5;
    const int h = lane >> 3;

    for (int d = warp; d < ND; d += nw) {
        int start = g_row[d];
        int cnt = g_count[d];
        float ed = __ldg(&g_edst[d * NH + h]);
        float4 acc = make_float4(0.f, 0.f, 0.f, 0.f);
        float sumex = 0.f;

        for (int j0 = 0; j0 < cnt; j0 += 32) {
            int myS = 0;
            if (j0 + lane < cnt) myS = __ldg(&g_ssorted[start + j0 + lane]);
            int lim = cnt - j0; if (lim > 32) lim = 32;
            #pragma unroll 4
            for (int jj = 0; jj < lim; jj++) {
                int s = __shfl_sync(0xffffffffu, myS, jj);
                float ev = __ldg(&g_esrc[s * NH + h]) + ed;
                ev = ev > 0.f ? ev : NEG * ev;
                float ex = __expf(ev);
                float4 f = *(const float4*)&g_fs[(size_t)s * HD + lane * 4];
                acc.x += f.x * ex;
                acc.y += f.y * ex;
                acc.z += f.z * ex;
                acc.w += f.w * ex;
                sumex += ex;
            }
        }
        float inv = sumex > 0.f ? 1.f / sumex : 0.f;
        float4 v;
        v.x = fmaxf(acc.x * inv, 0.f);
        v.y = fmaxf(acc.y * inv, 0.f);
        v.z = fmaxf(acc.z * inv, 0.f);
        v.w = fmaxf(acc.w * inv, 0.f);
        *(float4*)&out[(size_t)d * HD + lane * 4] = v;
    }
}

// ---------------------------------------------------------------------------
extern "C" void kernel_launch(void* const* d_in, const int* in_sizes, int n_in,
                              void* d_out, int out_size) {
    const float* feat_src = (const float*)d_in[0];
    const float* feat_dst = (const float*)d_in[1];
    const float* w_src    = (const float*)d_in[2];
    const float* w_dst    = (const float*)d_in[3];
    const float* attn     = (const float*)d_in[4];
    const int*   src_idx  = (const int*)d_in[5];
    const int*   dst_idx  = (const int*)d_in[6];
    float* out = (float*)d_out;

    k_v<<<1, 256>>>(w_dst, attn);
    {
        int total = NS * NH / 4 + ND / 4;
        k_zero<<<(total + 255) / 256, 256>>>();
    }
    k_hist<<<(NE + 255) / 256, 256>>>(dst_idx);
    k_scan<<<1, SCAN_T>>>();
    k_scatter<<<(NE + 255) / 256, 256>>>(src_idx, dst_idx);
    k_gemm<<<(NS + 127) / 128, 256>>>(feat_src, w_src, attn, NS);
    k_e<<<(ND + 7) / 8, 256>>>(feat_dst, ND);
    k_gather<<<(ND + 7) / 8, 256>>>(out);
}